// round 16
// baseline (speedup 1.0000x reference)
#include <cuda_runtime.h>
#include <cuda_bf16.h>
#include <cstdint>

#define B_DIM   2048
#define IN_DIM  16384
#define OUT_DIM 16384

// ---------------- global scratch (static, no runtime alloc) ----------------
__device__ uint16_t g_xqT[(size_t)IN_DIM * B_DIM];   // transposed u16-quantized x (64MB)
__device__ uint32_t g_idxpack[OUT_DIM];              // ia | (ib<<16)
__device__ float4   g_coef[OUT_DIM];                 // (c0, ca*2^-16, cb*2^-16, cab*2^-32)
__device__ int      g_ready[33];                     // [0..31]: b-col groups, [32]: prep

__device__ __forceinline__ uint32_t quant16(float v) {
    return (uint32_t)fminf(fmaf(v, 65536.0f, 0.5f), 65535.0f);
}
// u16 halves of a u32 word -> exact floats, no I2F: PRMT + FADD.
__device__ __forceinline__ float code_lo(uint32_t w) {
    return __uint_as_float(__byte_perm(w, 0x4B00, 0x5410)) - 8388608.0f;
}
__device__ __forceinline__ float code_hi(uint32_t w) {
    return __uint_as_float(__byte_perm(w, 0x4B00, 0x5432)) - 8388608.0f;
}

__global__ void zero_kernel() {
    if (threadIdx.x < 33) g_ready[threadIdx.x] = 0;
}

// ---------------- fused pipeline kernel ----------------
// Grid order (in-order CTA dispatch makes the spin-waits deadlock-free):
//   [0, 64)            prep: 256 outputs/block
//   [64, 64+8192)      transpose: 64i x 64b tiles
//   [8256, 8256+8192)  main: 64n x 64b tiles, spins until its b-group is ready
#define PREPB   64
#define TPB     ((IN_DIM / 64) * (B_DIM / 64))      // 8192
#define MAINB   ((OUT_DIM / 64) * (B_DIM / 64))     // 8192
#define TS32    33                                   // transpose tile u32 stride
#define TSO     66                                   // main tile fp32 row stride

__global__ __launch_bounds__(256, 8)
void fused_kernel(const float* __restrict__ x,
                  const float* __restrict__ w,
                  const int* __restrict__ idx_a,
                  const int* __restrict__ idx_b,
                  float* __restrict__ out) {
    __shared__ uint32_t smem_buf[64 * TSO];          // 16896 B, shared by both paths
    const int t  = threadIdx.x;
    const int bx = blockIdx.x;

    if (bx < PREPB) {
        // ---- prep: softmax -> affine coefficients ----
        int n = bx * 256 + t;
        float p[16];
        const float4* wp = reinterpret_cast<const float4*>(w + (size_t)n * 16);
        float4 w0 = wp[0], w1 = wp[1], w2 = wp[2], w3 = wp[3];
        p[0]=w0.x; p[1]=w0.y; p[2]=w0.z; p[3]=w0.w;
        p[4]=w1.x; p[5]=w1.y; p[6]=w1.z; p[7]=w1.w;
        p[8]=w2.x; p[9]=w2.y; p[10]=w2.z; p[11]=w2.w;
        p[12]=w3.x; p[13]=w3.y; p[14]=w3.z; p[15]=w3.w;

        float m = p[0];
        #pragma unroll
        for (int i = 1; i < 16; i++) m = fmaxf(m, p[i]);
        float s = 0.f;
        #pragma unroll
        for (int i = 0; i < 16; i++) { p[i] = expf(p[i] - m); s += p[i]; }
        float inv = 1.0f / s;
        #pragma unroll
        for (int i = 0; i < 16; i++) p[i] *= inv;

        // gates = c0 + ca*a + cb*b + cab*ab
        float c0  = p[8]+p[9]+p[10]+p[11]+p[12]+p[13]+p[14]+p[15];
        float ca  = p[2]+p[3]+p[6]+p[7] - p[8]-p[9]-p[12]-p[13];
        float cb  = p[4]+p[5]+p[6]+p[7] - p[8]-p[9]-p[10]-p[11];
        float cab = p[1] - p[2] - p[4] - 2.0f*p[6] - p[7]
                  + p[8] + 2.0f*p[9] + p[11] + p[13] - p[14];

        g_idxpack[n] = (uint32_t)idx_a[n] | ((uint32_t)idx_b[n] << 16);
        const float S1 = 1.52587890625e-05f;         // 2^-16
        const float S2 = 2.3283064365386963e-10f;    // 2^-32
        g_coef[n] = make_float4(c0, ca * S1, cb * S1, cab * S2);

        __syncthreads();
        if (t == 0) { __threadfence(); atomicAdd(&g_ready[32], 1); }
        return;
    }

    if (bx < PREPB + TPB) {
        // ---- transpose: quantize 64i x 64b tile of x into g_xqT ----
        uint32_t* tile32 = smem_buf;                 // 64 x TS32
        const int tbx = bx - PREPB;
        const int i0 = (tbx & 255) * 64;
        const int g  = tbx >> 8;                     // b-col group 0..31
        const int b0 = g * 64;

        {
            const int c = t & 15;                    // i-quad
            const int r = t >> 4;                    // b-pair base 0..15
            float4 v0[2], v1[2];
            #pragma unroll
            for (int rr = 0; rr < 2; rr++) {
                int bp = r + 16 * rr;
                v0[rr] = __ldcs(reinterpret_cast<const float4*>(
                    x + (size_t)(b0 + 2*bp    ) * IN_DIM + i0 + 4*c));
                v1[rr] = __ldcs(reinterpret_cast<const float4*>(
                    x + (size_t)(b0 + 2*bp + 1) * IN_DIM + i0 + 4*c));
            }
            #pragma unroll
            for (int rr = 0; rr < 2; rr++) {
                int bp = r + 16 * rr;
                tile32[(4*c + 0) * TS32 + bp] = quant16(v0[rr].x) | (quant16(v1[rr].x) << 16);
                tile32[(4*c + 1) * TS32 + bp] = quant16(v0[rr].y) | (quant16(v1[rr].y) << 16);
                tile32[(4*c + 2) * TS32 + bp] = quant16(v0[rr].z) | (quant16(v1[rr].z) << 16);
                tile32[(4*c + 3) * TS32 + bp] = quant16(v0[rr].w) | (quant16(v1[rr].w) << 16);
            }
        }
        __syncthreads();
        {
            const int m2 = t & 15;
            const int ir = t >> 4;
            #pragma unroll
            for (int ii = 0; ii < 4; ii++) {
                int il = ir + 16 * ii;
                uint2 q;
                q.x = tile32[il * TS32 + 2*m2];
                q.y = tile32[il * TS32 + 2*m2 + 1];
                __stcg(reinterpret_cast<uint2*>(&g_xqT[(size_t)(i0 + il) * B_DIM + b0 + 4*m2]), q);
            }
        }
        __syncthreads();
        if (t == 0) { __threadfence(); atomicAdd(&g_ready[g], 1); }
        return;
    }

    // ---- main: 64 outputs x 64 batch tile ----
    {
        float* tileo = reinterpret_cast<float*>(smem_buf);   // 64 x TSO
        const int m  = bx - (PREPB + TPB);
        const int jb = m >> 8;                       // b-group 0..31
        const int n0 = (m & 255) * 64;
        const int b0 = jb * 64;

        if (t == 0) {
            volatile int* r = (volatile int*)g_ready;
            while (r[32] != PREPB) __nanosleep(64);
            while (r[jb] != 256)   __nanosleep(64);
            __threadfence();
        }
        __syncthreads();

        const int l   = t & 31;
        const int wpi = t >> 5;                      // warp 0..7

        #pragma unroll
        for (int q = 0; q < 8; q++) {
            const int nl = wpi * 8 + q;
            const int n  = n0 + nl;
            uint32_t ip = __ldg(&g_idxpack[n]);
            float4  c   = __ldg(&g_coef[n]);
            const uint32_t* ra = reinterpret_cast<const uint32_t*>(
                g_xqT + (size_t)(ip & 0xFFFFu) * B_DIM + b0);
            const uint32_t* rb = reinterpret_cast<const uint32_t*>(
                g_xqT + (size_t)(ip >> 16) * B_DIM + b0);

            uint32_t A = __ldcg(ra + l);
            uint32_t B = __ldcg(rb + l);
            float fa0 = code_lo(A), fa1 = code_hi(A);
            float fb0 = code_lo(B), fb1 = code_hi(B);
            float v0 = fmaf(fmaf(c.w, fb0, c.y), fa0, fmaf(c.z, fb0, c.x));
            float v1 = fmaf(fmaf(c.w, fb1, c.y), fa1, fmaf(c.z, fb1, c.x));
            *reinterpret_cast<float2*>(&tileo[nl * TSO + 2 * l]) = make_float2(v0, v1);
        }
        __syncthreads();

        // write-out: warp covers 32 consecutive n -> coalesced 128B streaming stores
        {
            const int nl = t & 63;
            const int bb = t >> 6;                   // 0..3
            #pragma unroll
            for (int j2 = 0; j2 < 16; j2++) {
                int bl = bb + 4 * j2;
                float v = tileo[nl * TSO + bl];
                __stcs(out + (size_t)(b0 + bl) * OUT_DIM + n0 + nl, v);
            }
        }
    }
}

extern "C" void kernel_launch(void* const* d_in, const int* in_sizes, int n_in,
                              void* d_out, int out_size) {
    const float* x   = (const float*)d_in[0];
    const float* w   = (const float*)d_in[1];
    const int*   ia  = (const int*)d_in[2];
    const int*   ib  = (const int*)d_in[3];
    float* out = (float*)d_out;

    zero_kernel<<<1, 64>>>();
    fused_kernel<<<PREPB + TPB + MAINB, 256>>>(x, w, ia, ib, out);
}